// round 13
// baseline (speedup 1.0000x reference)
#include <cuda_runtime.h>
#include <cuda_fp16.h>
#include <math.h>
#include <stdint.h>

#define B_  128
#define T_  64
#define F_  2048
#define H_  1024
#define M_  512
#define G4  4096   // 4*H
#define NA  4608   // 4H + M
#define K2  2048   // 2H

// ---------------- device scratch (no allocations allowed) -------------------
__device__ __align__(128) __half d_VidH[(size_t)B_*T_*F_];
__device__ __align__(128) __half d_VidL[(size_t)B_*T_*F_];
__device__ __align__(128) __half d_WembH[(size_t)H_*F_];
__device__ __align__(128) __half d_WembL[(size_t)H_*F_];
__device__ __align__(128) __half d_VH[(size_t)B_*T_*H_];     // relu(embed) split, rows b*T+t
__device__ __align__(128) __half d_VL[(size_t)B_*T_*H_];
__device__ __align__(128) __half d_WxH[(size_t)NA*H_];       // [W_ih1; Wsi]
__device__ __align__(128) __half d_WxL[(size_t)NA*H_];
__device__ __align__(128) __half d_WhH[(size_t)NA*H_];       // [W_hh1; Wsh]
__device__ __align__(128) __half d_WhL[(size_t)NA*H_];
__device__ __align__(128) __half d_WbH[(size_t)G4*K2];       // [W_ih2 | W_hh2]
__device__ __align__(128) __half d_WbL[(size_t)G4*K2];
__device__ __align__(128) __half d_AhH[B_*H_];               // h1 split (Y1 A)
__device__ __align__(128) __half d_AhL[B_*H_];
__device__ __align__(128) __half d_STH[B_*K2];               // [h1r*s | h2] (Y2 A, hi only)
__device__ __align__(128) __half d_STL[B_*K2];               // (unused)

__device__ float d_bx [NA];
__device__ float d_GXZ[(size_t)B_*T_*NA];    // rows t*B+b
__device__ float d_Y1 [B_*NA];
__device__ float d_Y2 [B_*G4];
__device__ float d_c1 [B_*H_];
__device__ float d_c2 [B_*H_];
__device__ unsigned int d_cnt[8];            // [0,1]=P1 tiles, [2,3]=P2 rows, [4,5]=P3 tiles, [6,7]=P4 rows

// ---------------- asm helpers ------------------------------------------------
__device__ __forceinline__ uint32_t s2u_(const void* p) {
    uint32_t a;
    asm("{ .reg .u64 t; cvta.to.shared.u64 t, %1; cvt.u32.u64 %0, t; }" : "=r"(a) : "l"(p));
    return a;
}
__device__ __forceinline__ void cp16_(uint32_t d, const void* s) {
    asm volatile("cp.async.cg.shared.global [%0], [%1], 16;" :: "r"(d), "l"(s));
}
__device__ __forceinline__ void ldsm4_(uint32_t a, uint32_t& r0, uint32_t& r1, uint32_t& r2, uint32_t& r3) {
    asm volatile("ldmatrix.sync.aligned.m8n8.x4.shared.b16 {%0,%1,%2,%3}, [%4];"
                 : "=r"(r0), "=r"(r1), "=r"(r2), "=r"(r3) : "r"(a));
}
__device__ __forceinline__ void hmma_(float* c, const uint32_t* a, const uint32_t* b) {
    asm volatile("mma.sync.aligned.m16n8k16.row.col.f32.f16.f16.f32 "
                 "{%0,%1,%2,%3}, {%4,%5,%6,%7}, {%8,%9}, {%0,%1,%2,%3};"
                 : "+f"(c[0]), "+f"(c[1]), "+f"(c[2]), "+f"(c[3])
                 : "r"(a[0]), "r"(a[1]), "r"(a[2]), "r"(a[3]), "r"(b[0]), "r"(b[1]));
}
__device__ __forceinline__ float sigm(float x) { return 1.f / (1.f + expf(-x)); }

// ---------------- precompute HMMA GEMM (64x128 tiles) ------------------------
// PASSES=3: HH+HL+LH; PASSES=2: HH+HL (A hi only).
constexpr int STAGE_B = 30720;
constexpr int SMEM_TOT = 2 * STAGE_B;
constexpr int OB_B = 10240;

template<int HAS_BIAS, int RELU, int SPLIT_OUT, int PASSES>
__global__ __launch_bounds__(256)
void gemm_h(const __half* __restrict__ AH, const __half* __restrict__ AL,
            size_t aS1, size_t aS2, int lda,
            const __half* __restrict__ BH, const __half* __restrict__ BL,
            float* __restrict__ C,
            const float* __restrict__ bias,
            __half* __restrict__ OH, __half* __restrict__ OL,
            int K, int N, int bxOff)
{
    extern __shared__ __align__(128) char sm[];
    const uint32_t sb = s2u_(sm);
    const int tid  = threadIdx.x;
    const int lane = tid & 31;
    const int wid  = tid >> 5;
    const int wm   = wid & 1;
    const int wn   = wid >> 1;
    const int bx   = blockIdx.x + bxOff, by = blockIdx.y;

    const size_t aOff = (size_t)(by & 1) * aS1 + (size_t)(by >> 1) * aS2;
    const __half* gAH = AH + aOff;
    const __half* gAL = AL + aOff;
    const __half* gBH = BH + (size_t)bx * 128 * K;
    const __half* gBL = BL + (size_t)bx * 128 * K;

    float acc[2][4][4];
#pragma unroll
    for (int i = 0; i < 2; i++)
#pragma unroll
        for (int j = 0; j < 4; j++)
#pragma unroll
            for (int q = 0; q < 4; q++) acc[i][j][q] = 0.f;

    auto load_stage = [&](int p, int kt) {
        const uint32_t dst = sb + p * STAGE_B;
        const int k0 = kt * 32;
#pragma unroll
        for (int i = 0; i < 2; i++) {
            int c = tid * 2 + i;
            int row = c >> 2, col = c & 3;
            if (PASSES == 3 || row < 64) {
                const __half* src = (row < 64) ? (gAH + (size_t)row * lda)
                                               : (gAL + (size_t)(row - 64) * lda);
                cp16_(dst + row * 80 + col * 16, src + k0 + col * 8);
            }
        }
#pragma unroll
        for (int i = 0; i < 4; i++) {
            int c = tid * 4 + i;
            int row = c >> 2, col = c & 3;
            const __half* src = (row < 128) ? (gBH + (size_t)row * K)
                                            : (gBL + (size_t)(row - 128) * K);
            cp16_(dst + OB_B + row * 80 + col * 16, src + k0 + col * 8);
        }
        asm volatile("cp.async.commit_group;" ::: "memory");
    };

    const int KT = K / 32;
    load_stage(0, 0);
    const int rsel = lane & 15, csel = lane >> 4;

    for (int kt = 0; kt < KT; kt++) {
        const int p = kt & 1;
        if (kt + 1 < KT) {
            load_stage(p ^ 1, kt + 1);
            asm volatile("cp.async.wait_group 1;" ::: "memory");
        } else {
            asm volatile("cp.async.wait_group 0;" ::: "memory");
        }
        __syncthreads();
        const uint32_t stg = sb + p * STAGE_B;
#pragma unroll
        for (int h = 0; h < 2; h++) {
            uint32_t aH[2][4], aL[2][4], bHf[4][2], bLf[4][2];
#pragma unroll
            for (int mi = 0; mi < 2; mi++) {
                int row = wm * 32 + mi * 16 + rsel;
                uint32_t ad = stg + row * 80 + h * 32 + csel * 16;
                ldsm4_(ad, aH[mi][0], aH[mi][1], aH[mi][2], aH[mi][3]);
                if (PASSES == 3)
                    ldsm4_(ad + 5120, aL[mi][0], aL[mi][1], aL[mi][2], aL[mi][3]);
            }
#pragma unroll
            for (int g = 0; g < 2; g++) {
                int row = wn * 32 + g * 16 + rsel;
                uint32_t bd = stg + OB_B + row * 80 + h * 32 + csel * 16;
                uint32_t t0, t1, t2, t3;
                ldsm4_(bd, t0, t1, t2, t3);
                bHf[g*2][0] = t0; bHf[g*2][1] = t2; bHf[g*2+1][0] = t1; bHf[g*2+1][1] = t3;
                ldsm4_(bd + 10240, t0, t1, t2, t3);
                bLf[g*2][0] = t0; bLf[g*2][1] = t2; bLf[g*2+1][0] = t1; bLf[g*2+1][1] = t3;
            }
#pragma unroll
            for (int mi = 0; mi < 2; mi++)
#pragma unroll
                for (int ni = 0; ni < 4; ni++) {
                    hmma_(acc[mi][ni], aH[mi], bHf[ni]);
                    hmma_(acc[mi][ni], aH[mi], bLf[ni]);
                    if (PASSES == 3)
                        hmma_(acc[mi][ni], aL[mi], bHf[ni]);
                }
        }
        __syncthreads();
    }

#pragma unroll
    for (int mi = 0; mi < 2; mi++)
#pragma unroll
        for (int ni = 0; ni < 4; ni++) {
            const int row0 = by * 64 + wm * 32 + mi * 16 + (lane >> 2);
            const int col  = bx * 128 + wn * 32 + ni * 8 + (lane & 3) * 2;
            float v[4];
#pragma unroll
            for (int q = 0; q < 4; q++) v[q] = acc[mi][ni][q];
            if (HAS_BIAS) {
                float b0 = bias[col], b1 = bias[col + 1];
                v[0] += b0; v[1] += b1; v[2] += b0; v[3] += b1;
            }
            if (RELU) {
#pragma unroll
                for (int q = 0; q < 4; q++) v[q] = fmaxf(v[q], 0.f);
            }
            if (SPLIT_OUT) {
#pragma unroll
                for (int q = 0; q < 4; q++) {
                    int r = row0 + (q >> 1) * 8, c = col + (q & 1);
                    __half hi = __float2half(v[q]);
                    __half lo = __float2half(v[q] - __half2float(hi));
                    OH[(size_t)r * N + c] = hi;
                    OL[(size_t)r * N + c] = lo;
                }
            } else {
                *reinterpret_cast<float2*>(&C[(size_t)row0 * N + col])       = make_float2(v[0], v[1]);
                *reinterpret_cast<float2*>(&C[(size_t)(row0 + 8) * N + col]) = make_float2(v[2], v[3]);
            }
        }
}

// ---------------- persistent scan: 64x32 tiles, 8 warps (4M x 2N), 3-stage ---
// stage: A 128 rows (64 hi + 64 lo) x 80B = 10240; B 64 rows (32 hi + 32 lo) x 80B = 5120.
constexpr int SSTG = 15360;

struct ScanSmem {
    __align__(128) char stg[3][SSTG];
    float red[256];
};

template<int PASSES>
__device__ __forceinline__ void tile_mm64(
    const __half* __restrict__ AH, const __half* __restrict__ AL, int lda,
    const __half* __restrict__ BH, const __half* __restrict__ BL, int ldb,
    int KT, uint32_t sbase, float acc[2][4],
    int tid, int wm2, int wn2, int rsel, int csel)
{
    auto load_stage = [&](int p, int kt) {
        const uint32_t dst = sbase + p * SSTG;
        const int k0 = kt * 32;
        {   // A hi: 64 rows x 4 chunks = 256, one per thread
            int row = tid >> 2, col = tid & 3;
            cp16_(dst + row * 80 + col * 16, AH + (size_t)row * lda + k0 + col * 8);
            if (PASSES == 3)   // A lo at stage rows 64..127
                cp16_(dst + (64 + row) * 80 + col * 16, AL + (size_t)row * lda + k0 + col * 8);
        }
        {   // B: 64 rows (32 hi + 32 lo) x 4 = 256 chunks, one per thread
            int row = tid >> 2, col = tid & 3;
            const __half* src = (row < 32) ? BH + (size_t)row * ldb
                                           : BL + (size_t)(row - 32) * ldb;
            cp16_(dst + 10240 + row * 80 + col * 16, src + k0 + col * 8);
        }
        asm volatile("cp.async.commit_group;" ::: "memory");
    };

    load_stage(0, 0);
    if (KT > 1) load_stage(1, 1);

    for (int kt = 0; kt < KT; kt++) {
        if (kt + 2 < KT) {
            load_stage((kt + 2) % 3, kt + 2);
            asm volatile("cp.async.wait_group 2;" ::: "memory");
        } else if (kt + 1 < KT) {
            asm volatile("cp.async.wait_group 1;" ::: "memory");
        } else {
            asm volatile("cp.async.wait_group 0;" ::: "memory");
        }
        __syncthreads();

        const uint32_t stg = sbase + (kt % 3) * SSTG;
#pragma unroll
        for (int h = 0; h < 2; h++) {
            uint32_t aH[4], aL[4], bH[2][2], bL[2][2];
            {
                uint32_t ad = stg + (wm2 * 16 + rsel) * 80 + h * 32 + csel * 16;
                ldsm4_(ad, aH[0], aH[1], aH[2], aH[3]);
                if (PASSES == 3)
                    ldsm4_(ad + 5120, aL[0], aL[1], aL[2], aL[3]);
            }
            {
                uint32_t bd = stg + 10240 + (wn2 * 16 + rsel) * 80 + h * 32 + csel * 16;
                uint32_t t0, t1, t2, t3;
                ldsm4_(bd, t0, t1, t2, t3);
                bH[0][0] = t0; bH[0][1] = t2; bH[1][0] = t1; bH[1][1] = t3;
                ldsm4_(bd + 2560, t0, t1, t2, t3);
                bL[0][0] = t0; bL[0][1] = t2; bL[1][0] = t1; bL[1][1] = t3;
            }
#pragma unroll
            for (int ni = 0; ni < 2; ni++) {
                hmma_(acc[ni], aH, bH[ni]);
                hmma_(acc[ni], aH, bL[ni]);
                if (PASSES == 3)
                    hmma_(acc[ni], aL, bH[ni]);
            }
        }
        __syncthreads();
    }
}

__global__ __launch_bounds__(256, 2)
void scan_persist(const float* __restrict__ vs, float* __restrict__ out)
{
    __shared__ ScanSmem sm;
    const uint32_t sbase = s2u_(&sm.stg[0][0]);
    const int tid  = threadIdx.x;
    const int lane = tid & 31;
    const int wid  = tid >> 5;
    const int wm2  = wid & 3, wn2 = wid >> 2;
    const int rsel = lane & 15, csel = lane >> 4;
    const int cta  = blockIdx.x;
    const int G    = gridDim.x;

    // acquire: spin until counter >= target, then fence
    auto waitc = [&](int ci, unsigned int target) {
        if (tid == 0)
            while (*((volatile unsigned int*)&d_cnt[ci]) < target) { }
        __syncthreads();
        __threadfence();
    };
    // release: fence all threads' writes, then bump counter
    auto signal = [&](int ci) {
        __threadfence();
        __syncthreads();
        if (tid == 0) atomicAdd(&d_cnt[ci], 1u);
    };

    // LSTM2 + c2/h2 commit for data step tm1 (= t-1)
    auto do_p4 = [&](int tm1, bool last) {
        const int b = cta - (G - B_);
        if (b >= 0 && b < B_) {
            const int m = b >> 6;
            waitc(4 + m, (unsigned)(tm1 + 1) * 128);   // Y2(tm1) done + P3(tm1) STH readers done
            const float* Yb = d_Y2 + (size_t)b * G4;
            for (int j = tid; j < H_; j += 256) {
                const int idx = b * H_ + j;
                float gi = Yb[j], gf = Yb[H_ + j], gg = Yb[2 * H_ + j], go = Yb[3 * H_ + j];
                float c = sigm(gf) * d_c2[idx] + sigm(gi) * tanhf(gg);
                float h = sigm(go) * tanhf(c);
                d_c2[idx] = c;
                d_STH[b * K2 + H_ + j] = __float2half(h);
                if (last) out[idx] = h;
            }
            signal(6 + m);
        }
    };

    for (int t = 0; t < T_; t++) {
        // ---- P4(t-1): LSTM2 commit (overlaps with P1 on other CTAs)
        if (t > 0) do_p4(t - 1, false);

        // ---- P1: Y1 = h1 @ [Whh1;Wsh]^T + GXZ[t]  (288 tiles of 64x32)
        for (int tile = cta; tile < 288; tile += G) {
            const int m = tile & 1, n = tile >> 1;
            waitc(2 + m, (unsigned)t * 64);            // P2(t-1) group m done (Ah ready, Y1 free)
            float acc[2][4];
#pragma unroll
            for (int j = 0; j < 2; j++)
#pragma unroll
                for (int q = 0; q < 4; q++) acc[j][q] = 0.f;
            if (n >= 128)
                tile_mm64<3>(d_AhH + (size_t)(m * 64) * H_, d_AhL + (size_t)(m * 64) * H_, H_,
                             d_WhH + (size_t)(n * 32) * H_, d_WhL + (size_t)(n * 32) * H_, H_,
                             H_ / 32, sbase, acc, tid, wm2, wn2, rsel, csel);
            else
                tile_mm64<2>(d_AhH + (size_t)(m * 64) * H_, d_AhL + (size_t)(m * 64) * H_, H_,
                             d_WhH + (size_t)(n * 32) * H_, d_WhL + (size_t)(n * 32) * H_, H_,
                             H_ / 32, sbase, acc, tid, wm2, wn2, rsel, csel);
            const float* gx = d_GXZ + (size_t)t * B_ * NA;
#pragma unroll
            for (int ni = 0; ni < 2; ni++) {
                const int r0 = m * 64 + wm2 * 16 + (lane >> 2);
                const int c0 = n * 32 + wn2 * 16 + ni * 8 + (lane & 3) * 2;
                float2 g0 = *reinterpret_cast<const float2*>(&gx[(size_t)r0 * NA + c0]);
                float2 g1 = *reinterpret_cast<const float2*>(&gx[(size_t)(r0 + 8) * NA + c0]);
                *reinterpret_cast<float2*>(&d_Y1[(size_t)r0 * NA + c0]) =
                    make_float2(acc[ni][0] + g0.x, acc[ni][1] + g0.y);
                *reinterpret_cast<float2*>(&d_Y1[(size_t)(r0 + 8) * NA + c0]) =
                    make_float2(acc[ni][2] + g1.x, acc[ni][3] + g1.y);
            }
            signal(0 + m);
        }

        // ---- P2: boundary gate + LSTM1 + state commit
        for (int b = cta; b < B_; b += G) {
            const int m = b >> 6;
            waitc(0 + m, (unsigned)(t + 1) * 144);     // Y1(t) group m done
            waitc(4 + m, (unsigned)t * 128);           // P3(t-1) STH readers done
            const float* Yb = d_Y1 + (size_t)b * NA;
            float p = Yb[G4 + tid] * vs[tid] + Yb[G4 + 256 + tid] * vs[256 + tid];
            sm.red[tid] = p;
            __syncthreads();
            for (int off = 128; off > 0; off >>= 1) {
                if (tid < off) sm.red[tid] += sm.red[tid + off];
                __syncthreads();
            }
            float s = rintf(1.f / (1.f + expf(-sm.red[0])));
            __syncthreads();
            for (int j = tid; j < H_; j += 256) {
                const int idx = b * H_ + j;
                float gi = Yb[j], gf = Yb[H_ + j], gg = Yb[2 * H_ + j], go = Yb[3 * H_ + j];
                float c = sigm(gf) * d_c1[idx] + sigm(gi) * tanhf(gg);
                float h = sigm(go) * tanhf(c);
                d_STH[b * K2 + j] = __float2half(h * s);
                float h1n = h * (1.f - s);
                d_c1[idx] = c * (1.f - s);
                __half hi = __float2half(h1n);
                __half lo = __float2half(h1n - __half2float(hi));
                d_AhH[idx] = hi;
                d_AhL[idx] = lo;
            }
            signal(2 + m);
        }

        // ---- P3: Y2 = [h1r*s | h2] @ [Wih2|Whh2]^T  (256 tiles of 64x32), 2-pass
        for (int tile = cta; tile < 256; tile += G) {
            const int m = tile & 1, n = tile >> 1;
            waitc(2 + m, (unsigned)(t + 1) * 64);      // ST lo-half (P2(t)) ready
            waitc(6 + m, (unsigned)t * 64);            // ST h2-half (P4(t)) ready + Y2 free
            float acc[2][4];
#pragma unroll
            for (int j = 0; j < 2; j++)
#pragma unroll
                for (int q = 0; q < 4; q++) acc[j][q] = 0.f;
            tile_mm64<2>(d_STH + (size_t)(m * 64) * K2, d_STL + (size_t)(m * 64) * K2, K2,
                         d_WbH + (size_t)(n * 32) * K2, d_WbL + (size_t)(n * 32) * K2, K2,
                         K2 / 32, sbase, acc, tid, wm2, wn2, rsel, csel);
#pragma unroll
            for (int ni = 0; ni < 2; ni++) {
                const int r0 = m * 64 + wm2 * 16 + (lane >> 2);
                const int c0 = n * 32 + wn2 * 16 + ni * 8 + (lane & 3) * 2;
                *reinterpret_cast<float2*>(&d_Y2[(size_t)r0 * G4 + c0]) =
                    make_float2(acc[ni][0], acc[ni][1]);
                *reinterpret_cast<float2*>(&d_Y2[(size_t)(r0 + 8) * G4 + c0]) =
                    make_float2(acc[ni][2], acc[ni][3]);
            }
            signal(4 + m);
        }
    }

    // trailing LSTM2 for t = T-1 (writes final output)
    do_p4(T_ - 1, true);
}

// ---------------- split / pack / zero kernels --------------------------------
__global__ void split_w(const float* __restrict__ S1, const float* __restrict__ S2,
                        __half* __restrict__ Hh, __half* __restrict__ Ll,
                        int KSHIFT, int mode, size_t total)
{
    size_t idx = (size_t)blockIdx.x * blockDim.x + threadIdx.x;
    if (idx >= total) return;
    const int K = 1 << KSHIFT;
    const int n = (int)(idx >> KSHIFT);
    const int k = (int)(idx & (K - 1));
    float v;
    if (mode == 0)      v = (n < G4) ? S1[idx] : S2[idx - (size_t)G4 * K];
    else if (mode == 1) v = (k < H_) ? S1[((size_t)n << 10) + k] : S2[((size_t)n << 10) + k - H_];
    else                v = S1[idx];
    __half hi = __float2half(v);
    __half lo = __float2half(v - __half2float(hi));
    Hh[idx] = hi; Ll[idx] = lo;
}

__global__ void pack_bias(const float* __restrict__ b1, const float* __restrict__ bbd)
{
    int i = blockIdx.x * blockDim.x + threadIdx.x;
    if (i < NA) d_bx[i] = (i < G4) ? b1[i] : bbd[i - G4];
}

__global__ void zero_state()
{
    int i = blockIdx.x * blockDim.x + threadIdx.x;
    __half z = __float2half(0.f);
    if (i < B_ * H_) { d_c1[i] = 0.f; d_c2[i] = 0.f; d_AhH[i] = z; d_AhL[i] = z; }
    if (i < B_ * K2) { d_STH[i] = z; d_STL[i] = z; }
    if (i < 8) d_cnt[i] = 0u;
}

// ---------------- launch -----------------------------------------------------
extern "C" void kernel_launch(void* const* d_in, const int* in_sizes, int n_in,
                              void* d_out, int out_size)
{
    const float* video = (const float*)d_in[0];
    const float* Wemb  = (const float*)d_in[1];
    const float* bemb  = (const float*)d_in[2];
    const float* Wih1  = (const float*)d_in[3];
    const float* Whh1  = (const float*)d_in[4];
    const float* b1    = (const float*)d_in[5];
    const float* Wsi   = (const float*)d_in[6];
    const float* Wsh   = (const float*)d_in[7];
    const float* bbd   = (const float*)d_in[8];
    const float* vs    = (const float*)d_in[9];
    const float* Wih2  = (const float*)d_in[10];
    const float* Whh2  = (const float*)d_in[11];

    __half *pVidH,*pVidL,*pWembH,*pWembL,*pVH,*pVL,*pWxH,*pWxL,*pWhH,*pWhL,*pWbH,*pWbL;
    float *pbx,*pGXZ;
    cudaGetSymbolAddress((void**)&pVidH, d_VidH);  cudaGetSymbolAddress((void**)&pVidL, d_VidL);
    cudaGetSymbolAddress((void**)&pWembH,d_WembH); cudaGetSymbolAddress((void**)&pWembL,d_WembL);
    cudaGetSymbolAddress((void**)&pVH,   d_VH);    cudaGetSymbolAddress((void**)&pVL,   d_VL);
    cudaGetSymbolAddress((void**)&pWxH,  d_WxH);   cudaGetSymbolAddress((void**)&pWxL,  d_WxL);
    cudaGetSymbolAddress((void**)&pWhH,  d_WhH);   cudaGetSymbolAddress((void**)&pWhL,  d_WhL);
    cudaGetSymbolAddress((void**)&pWbH,  d_WbH);   cudaGetSymbolAddress((void**)&pWbL,  d_WbL);
    cudaGetSymbolAddress((void**)&pbx,   d_bx);
    cudaGetSymbolAddress((void**)&pGXZ,  d_GXZ);

    cudaFuncSetAttribute(gemm_h<1,1,1,3>, cudaFuncAttributeMaxDynamicSharedMemorySize, SMEM_TOT);
    cudaFuncSetAttribute(gemm_h<1,0,0,2>, cudaFuncAttributeMaxDynamicSharedMemorySize, SMEM_TOT);
    cudaFuncSetAttribute(gemm_h<1,0,0,3>, cudaFuncAttributeMaxDynamicSharedMemorySize, SMEM_TOT);
    cudaFuncSetAttribute(scan_persist, cudaFuncAttributePreferredSharedMemoryCarveout,
                         cudaSharedmemCarveoutMaxShared);

    // deterministic grid: all CTAs resident (required by the spin protocol)
    int nsm = 148, occ = 2;
    cudaDeviceGetAttribute(&nsm, cudaDevAttrMultiProcessorCount, 0);
    cudaOccupancyMaxActiveBlocksPerMultiprocessor(&occ, scan_persist, 256, 0);
    if (occ < 1) occ = 1;
    if (occ > 2) occ = 2;
    const int G = nsm * occ;

    zero_state<<<(B_*K2 + 255) / 256, 256>>>();
    pack_bias<<<(NA + 255) / 256, 256>>>(b1, bbd);
    {
        size_t n;
        n = (size_t)H_ * F_;   split_w<<<(int)((n + 255) / 256), 256>>>(Wemb,  nullptr, pWembH, pWembL, 11, 2, n);
        n = (size_t)NA * H_;   split_w<<<(int)((n + 255) / 256), 256>>>(Wih1,  Wsi,     pWxH,   pWxL,   10, 0, n);
        n = (size_t)NA * H_;   split_w<<<(int)((n + 255) / 256), 256>>>(Whh1,  Wsh,     pWhH,   pWhL,   10, 0, n);
        n = (size_t)G4 * K2;   split_w<<<(int)((n + 255) / 256), 256>>>(Wih2,  Whh2,    pWbH,   pWbL,   11, 1, n);
        n = (size_t)B_*T_*F_;  split_w<<<(int)((n + 255) / 256), 256>>>(video, nullptr, pVidH,  pVidL,  11, 2, n);
    }

    // V = relu(video @ Wemb^T + bemb) -> fp16 split (rows b*T+t), 3-pass
    gemm_h<1,1,1,3><<<dim3(H_/128, (B_*T_)/64), 256, SMEM_TOT>>>(
        pVidH, pVidL, (size_t)64 * F_, (size_t)128 * F_, F_,
        pWembH, pWembL, nullptr, bemb, pVH, pVL, F_, H_, 0);
    // GXZ[t*B+b] = V[b*T+t] @ [Wih1;Wsi]^T + [b1;b_bd]
    // cols 0..4095 (LSTM1 x-gates): 2-pass; cols 4096..4607 (gate): 3-pass
    gemm_h<1,0,0,2><<<dim3(32, (B_*T_)/64), 256, SMEM_TOT>>>(
        pVH, pVL, (size_t)64 * T_ * H_, (size_t)H_, T_ * H_,
        pWxH, pWxL, pGXZ, pbx, nullptr, nullptr, H_, NA, 0);
    gemm_h<1,0,0,3><<<dim3(4, (B_*T_)/64), 256, SMEM_TOT>>>(
        pVH, pVL, (size_t)64 * T_ * H_, (size_t)H_, T_ * H_,
        pWxH, pWxL, pGXZ, pbx, nullptr, nullptr, H_, NA, 32);

    // persistent dataflow scan over T (no global barriers)
    scan_persist<<<G, 256>>>(vs, (float*)d_out);
}

// round 14
// speedup vs baseline: 1.0191x; 1.0191x over previous
#include <cuda_runtime.h>
#include <cuda_fp16.h>
#include <math.h>
#include <stdint.h>

#define B_  128
#define T_  64
#define F_  2048
#define H_  1024
#define M_  512
#define G4  4096   // 4*H
#define NA  4608   // 4H + M
#define K2  2048   // 2H

// ---------------- device scratch (no allocations allowed) -------------------
__device__ __align__(128) __half d_VidH[(size_t)B_*T_*F_];
__device__ __align__(128) __half d_VidL[(size_t)B_*T_*F_];
__device__ __align__(128) __half d_WembH[(size_t)H_*F_];
__device__ __align__(128) __half d_WembL[(size_t)H_*F_];
__device__ __align__(128) __half d_VH[(size_t)B_*T_*H_];     // relu(embed) split, rows b*T+t
__device__ __align__(128) __half d_VL[(size_t)B_*T_*H_];
__device__ __align__(128) __half d_WxH[(size_t)NA*H_];       // [W_ih1; Wsi]
__device__ __align__(128) __half d_WxL[(size_t)NA*H_];
__device__ __align__(128) __half d_WhH[(size_t)NA*H_];       // [W_hh1; Wsh]
__device__ __align__(128) __half d_WhL[(size_t)NA*H_];
__device__ __align__(128) __half d_WbH[(size_t)G4*K2];       // [W_ih2 | W_hh2]
__device__ __align__(128) __half d_WbL[(size_t)G4*K2];
__device__ __align__(128) __half d_AhH[B_*H_];               // h1 split (Y1 A)
__device__ __align__(128) __half d_AhL[B_*H_];
__device__ __align__(128) __half d_STH[B_*K2];               // [h1r*s | h2] (Y2 A, hi only)

__device__ float d_bx [NA];
__device__ float d_GXZ[(size_t)B_*T_*NA];    // rows t*B+b
__device__ float d_Y1 [B_*NA];
__device__ float d_Y2 [B_*G4];
__device__ float d_c1 [B_*H_];
__device__ float d_c2 [B_*H_];
__device__ float d_s  [B_];
__device__ unsigned int d_bars[260];

// ---------------- asm helpers ------------------------------------------------
__device__ __forceinline__ uint32_t s2u_(const void* p) {
    uint32_t a;
    asm("{ .reg .u64 t; cvta.to.shared.u64 t, %1; cvt.u32.u64 %0, t; }" : "=r"(a) : "l"(p));
    return a;
}
__device__ __forceinline__ void cp16_(uint32_t d, const void* s) {
    asm volatile("cp.async.cg.shared.global [%0], [%1], 16;" :: "r"(d), "l"(s));
}
__device__ __forceinline__ void ldsm4_(uint32_t a, uint32_t& r0, uint32_t& r1, uint32_t& r2, uint32_t& r3) {
    asm volatile("ldmatrix.sync.aligned.m8n8.x4.shared.b16 {%0,%1,%2,%3}, [%4];"
                 : "=r"(r0), "=r"(r1), "=r"(r2), "=r"(r3) : "r"(a));
}
__device__ __forceinline__ void hmma_(float* c, const uint32_t* a, const uint32_t* b) {
    asm volatile("mma.sync.aligned.m16n8k16.row.col.f32.f16.f16.f32 "
                 "{%0,%1,%2,%3}, {%4,%5,%6,%7}, {%8,%9}, {%0,%1,%2,%3};"
                 : "+f"(c[0]), "+f"(c[1]), "+f"(c[2]), "+f"(c[3])
                 : "r"(a[0]), "r"(a[1]), "r"(a[2]), "r"(a[3]), "r"(b[0]), "r"(b[1]));
}
__device__ __forceinline__ float sigm(float x) { return 1.f / (1.f + expf(-x)); }

// ---------------- precompute HMMA GEMM (64x128 tiles) ------------------------
// PASSES=3: HH+HL+LH; PASSES=2: HH+HL (A hi only).
constexpr int STAGE_B = 30720;
constexpr int SMEM_TOT = 2 * STAGE_B;
constexpr int OB_B = 10240;

template<int HAS_BIAS, int RELU, int SPLIT_OUT, int PASSES>
__global__ __launch_bounds__(256)
void gemm_h(const __half* __restrict__ AH, const __half* __restrict__ AL,
            size_t aS1, size_t aS2, int lda,
            const __half* __restrict__ BH, const __half* __restrict__ BL,
            float* __restrict__ C,
            const float* __restrict__ bias,
            __half* __restrict__ OH, __half* __restrict__ OL,
            int K, int N, int bxOff)
{
    extern __shared__ __align__(128) char sm[];
    const uint32_t sb = s2u_(sm);
    const int tid  = threadIdx.x;
    const int lane = tid & 31;
    const int wid  = tid >> 5;
    const int wm   = wid & 1;
    const int wn   = wid >> 1;
    const int bx   = blockIdx.x + bxOff, by = blockIdx.y;

    const size_t aOff = (size_t)(by & 1) * aS1 + (size_t)(by >> 1) * aS2;
    const __half* gAH = AH + aOff;
    const __half* gAL = AL + aOff;
    const __half* gBH = BH + (size_t)bx * 128 * K;
    const __half* gBL = BL + (size_t)bx * 128 * K;

    float acc[2][4][4];
#pragma unroll
    for (int i = 0; i < 2; i++)
#pragma unroll
        for (int j = 0; j < 4; j++)
#pragma unroll
            for (int q = 0; q < 4; q++) acc[i][j][q] = 0.f;

    auto load_stage = [&](int p, int kt) {
        const uint32_t dst = sb + p * STAGE_B;
        const int k0 = kt * 32;
#pragma unroll
        for (int i = 0; i < 2; i++) {
            int c = tid * 2 + i;
            int row = c >> 2, col = c & 3;
            if (PASSES == 3 || row < 64) {
                const __half* src = (row < 64) ? (gAH + (size_t)row * lda)
                                               : (gAL + (size_t)(row - 64) * lda);
                cp16_(dst + row * 80 + col * 16, src + k0 + col * 8);
            }
        }
#pragma unroll
        for (int i = 0; i < 4; i++) {
            int c = tid * 4 + i;
            int row = c >> 2, col = c & 3;
            const __half* src = (row < 128) ? (gBH + (size_t)row * K)
                                            : (gBL + (size_t)(row - 128) * K);
            cp16_(dst + OB_B + row * 80 + col * 16, src + k0 + col * 8);
        }
        asm volatile("cp.async.commit_group;" ::: "memory");
    };

    const int KT = K / 32;
    load_stage(0, 0);
    const int rsel = lane & 15, csel = lane >> 4;

    for (int kt = 0; kt < KT; kt++) {
        const int p = kt & 1;
        if (kt + 1 < KT) {
            load_stage(p ^ 1, kt + 1);
            asm volatile("cp.async.wait_group 1;" ::: "memory");
        } else {
            asm volatile("cp.async.wait_group 0;" ::: "memory");
        }
        __syncthreads();
        const uint32_t stg = sb + p * STAGE_B;
#pragma unroll
        for (int h = 0; h < 2; h++) {
            uint32_t aH[2][4], aL[2][4], bHf[4][2], bLf[4][2];
#pragma unroll
            for (int mi = 0; mi < 2; mi++) {
                int row = wm * 32 + mi * 16 + rsel;
                uint32_t ad = stg + row * 80 + h * 32 + csel * 16;
                ldsm4_(ad, aH[mi][0], aH[mi][1], aH[mi][2], aH[mi][3]);
                if (PASSES == 3)
                    ldsm4_(ad + 5120, aL[mi][0], aL[mi][1], aL[mi][2], aL[mi][3]);
            }
#pragma unroll
            for (int g = 0; g < 2; g++) {
                int row = wn * 32 + g * 16 + rsel;
                uint32_t bd = stg + OB_B + row * 80 + h * 32 + csel * 16;
                uint32_t t0, t1, t2, t3;
                ldsm4_(bd, t0, t1, t2, t3);
                bHf[g*2][0] = t0; bHf[g*2][1] = t2; bHf[g*2+1][0] = t1; bHf[g*2+1][1] = t3;
                ldsm4_(bd + 10240, t0, t1, t2, t3);
                bLf[g*2][0] = t0; bLf[g*2][1] = t2; bLf[g*2+1][0] = t1; bLf[g*2+1][1] = t3;
            }
#pragma unroll
            for (int mi = 0; mi < 2; mi++)
#pragma unroll
                for (int ni = 0; ni < 4; ni++) {
                    hmma_(acc[mi][ni], aH[mi], bHf[ni]);
                    hmma_(acc[mi][ni], aH[mi], bLf[ni]);
                    if (PASSES == 3)
                        hmma_(acc[mi][ni], aL[mi], bHf[ni]);
                }
        }
        __syncthreads();
    }

#pragma unroll
    for (int mi = 0; mi < 2; mi++)
#pragma unroll
        for (int ni = 0; ni < 4; ni++) {
            const int row0 = by * 64 + wm * 32 + mi * 16 + (lane >> 2);
            const int col  = bx * 128 + wn * 32 + ni * 8 + (lane & 3) * 2;
            float v[4];
#pragma unroll
            for (int q = 0; q < 4; q++) v[q] = acc[mi][ni][q];
            if (HAS_BIAS) {
                float b0 = bias[col], b1 = bias[col + 1];
                v[0] += b0; v[1] += b1; v[2] += b0; v[3] += b1;
            }
            if (RELU) {
#pragma unroll
                for (int q = 0; q < 4; q++) v[q] = fmaxf(v[q], 0.f);
            }
            if (SPLIT_OUT) {
#pragma unroll
                for (int q = 0; q < 4; q++) {
                    int r = row0 + (q >> 1) * 8, c = col + (q & 1);
                    __half hi = __float2half(v[q]);
                    __half lo = __float2half(v[q] - __half2float(hi));
                    OH[(size_t)r * N + c] = hi;
                    OL[(size_t)r * N + c] = lo;
                }
            } else {
                *reinterpret_cast<float2*>(&C[(size_t)row0 * N + col])       = make_float2(v[0], v[1]);
                *reinterpret_cast<float2*>(&C[(size_t)(row0 + 8) * N + col]) = make_float2(v[2], v[3]);
            }
        }
}

// ---------------- persistent scan: 64x32 tiles, 8 warps (4M x 2N), 3-stage ---
// stage: A 128 rows (64 hi + 64 lo) x 80B = 10240; B 64 rows (32 hi + 32 lo) x 80B = 5120.
constexpr int SSTG = 15360;

struct ScanSmem {
    __align__(128) char stg[3][SSTG];
    float red[256];
};

template<int PASSES>
__device__ __forceinline__ void tile_mm64(
    const __half* __restrict__ AH, const __half* __restrict__ AL, int lda,
    const __half* __restrict__ BH, const __half* __restrict__ BL, int ldb,
    int KT, uint32_t sbase, float acc[2][4],
    int tid, int wm2, int wn2, int rsel, int csel)
{
    auto load_stage = [&](int p, int kt) {
        const uint32_t dst = sbase + p * SSTG;
        const int k0 = kt * 32;
        {   // A hi: 64 rows x 4 chunks = 256, one per thread
            int row = tid >> 2, col = tid & 3;
            cp16_(dst + row * 80 + col * 16, AH + (size_t)row * lda + k0 + col * 8);
            if (PASSES == 3)   // A lo at stage rows 64..127
                cp16_(dst + (64 + row) * 80 + col * 16, AL + (size_t)row * lda + k0 + col * 8);
        }
        {   // B: 64 rows (32 hi + 32 lo) x 4 = 256 chunks, one per thread
            int row = tid >> 2, col = tid & 3;
            const __half* src = (row < 32) ? BH + (size_t)row * ldb
                                           : BL + (size_t)(row - 32) * ldb;
            cp16_(dst + 10240 + row * 80 + col * 16, src + k0 + col * 8);
        }
        asm volatile("cp.async.commit_group;" ::: "memory");
    };

    load_stage(0, 0);
    if (KT > 1) load_stage(1, 1);

    for (int kt = 0; kt < KT; kt++) {
        if (kt + 2 < KT) {
            load_stage((kt + 2) % 3, kt + 2);
            asm volatile("cp.async.wait_group 2;" ::: "memory");
        } else if (kt + 1 < KT) {
            asm volatile("cp.async.wait_group 1;" ::: "memory");
        } else {
            asm volatile("cp.async.wait_group 0;" ::: "memory");
        }
        __syncthreads();

        const uint32_t stg = sbase + (kt % 3) * SSTG;
#pragma unroll
        for (int h = 0; h < 2; h++) {
            uint32_t aH[4], aL[4], bH[2][2], bL[2][2];
            {
                uint32_t ad = stg + (wm2 * 16 + rsel) * 80 + h * 32 + csel * 16;
                ldsm4_(ad, aH[0], aH[1], aH[2], aH[3]);
                if (PASSES == 3)
                    ldsm4_(ad + 5120, aL[0], aL[1], aL[2], aL[3]);
            }
            {
                uint32_t bd = stg + 10240 + (wn2 * 16 + rsel) * 80 + h * 32 + csel * 16;
                uint32_t t0, t1, t2, t3;
                ldsm4_(bd, t0, t1, t2, t3);
                bH[0][0] = t0; bH[0][1] = t2; bH[1][0] = t1; bH[1][1] = t3;
                ldsm4_(bd + 2560, t0, t1, t2, t3);
                bL[0][0] = t0; bL[0][1] = t2; bL[1][0] = t1; bL[1][1] = t3;
            }
#pragma unroll
            for (int ni = 0; ni < 2; ni++) {
                hmma_(acc[ni], aH, bH[ni]);
                hmma_(acc[ni], aH, bL[ni]);
                if (PASSES == 3)
                    hmma_(acc[ni], aL, bH[ni]);
            }
        }
        __syncthreads();
    }
}

__global__ __launch_bounds__(256, 2)
void scan_persist(const float* __restrict__ vs, float* __restrict__ out)
{
    __shared__ ScanSmem sm;
    const uint32_t sbase = s2u_(&sm.stg[0][0]);
    const int tid  = threadIdx.x;
    const int lane = tid & 31;
    const int wid  = tid >> 5;
    const int wm2  = wid & 3, wn2 = wid >> 2;
    const int rsel = lane & 15, csel = lane >> 4;
    const int cta  = blockIdx.x;
    const int G    = gridDim.x;
    int bar = 0;

    auto gbar = [&]() {
        __threadfence();
        __syncthreads();
        if (tid == 0) {
            atomicAdd(&d_bars[bar], 1u);
            while (*((volatile unsigned int*)&d_bars[bar]) < (unsigned)G) { }
        }
        bar++;
        __syncthreads();
        __threadfence();
    };

    // LSTM2 + c2/h2 commit (runs inside the NEXT step's P1 phase)
    auto do_p4 = [&](bool last) {
        const int b = cta - (G - B_);
        if (b >= 0 && b < B_) {
            const float* Yb = d_Y2 + (size_t)b * G4;
            for (int j = tid; j < H_; j += 256) {
                const int idx = b * H_ + j;
                float gi = Yb[j], gf = Yb[H_ + j], gg = Yb[2 * H_ + j], go = Yb[3 * H_ + j];
                float c = sigm(gf) * d_c2[idx] + sigm(gi) * tanhf(gg);
                float h = sigm(go) * tanhf(c);
                d_c2[idx] = c;
                d_STH[b * K2 + H_ + j] = __float2half(h);
                if (last) out[idx] = h;
            }
        }
    };

    for (int t = 0; t < T_; t++) {
        // ---- phase A: P4(t-1) + P1: Y1 = h1 @ [Whh1;Wsh]^T + GXZ[t] (288 tiles 64x32)
        if (t > 0) do_p4(false);
        for (int tile = cta; tile < 288; tile += G) {
            const int m = tile & 1, n = tile >> 1;
            float acc[2][4];
#pragma unroll
            for (int j = 0; j < 2; j++)
#pragma unroll
                for (int q = 0; q < 4; q++) acc[j][q] = 0.f;
            if (n >= 128)
                tile_mm64<3>(d_AhH + (size_t)(m * 64) * H_, d_AhL + (size_t)(m * 64) * H_, H_,
                             d_WhH + (size_t)(n * 32) * H_, d_WhL + (size_t)(n * 32) * H_, H_,
                             H_ / 32, sbase, acc, tid, wm2, wn2, rsel, csel);
            else
                tile_mm64<2>(d_AhH + (size_t)(m * 64) * H_, d_AhL + (size_t)(m * 64) * H_, H_,
                             d_WhH + (size_t)(n * 32) * H_, d_WhL + (size_t)(n * 32) * H_, H_,
                             H_ / 32, sbase, acc, tid, wm2, wn2, rsel, csel);
            const float* gx = d_GXZ + (size_t)t * B_ * NA;
#pragma unroll
            for (int ni = 0; ni < 2; ni++) {
                const int r0 = m * 64 + wm2 * 16 + (lane >> 2);
                const int c0 = n * 32 + wn2 * 16 + ni * 8 + (lane & 3) * 2;
                float2 g0 = *reinterpret_cast<const float2*>(&gx[(size_t)r0 * NA + c0]);
                float2 g1 = *reinterpret_cast<const float2*>(&gx[(size_t)(r0 + 8) * NA + c0]);
                *reinterpret_cast<float2*>(&d_Y1[(size_t)r0 * NA + c0]) =
                    make_float2(acc[ni][0] + g0.x, acc[ni][1] + g0.y);
                *reinterpret_cast<float2*>(&d_Y1[(size_t)(r0 + 8) * NA + c0]) =
                    make_float2(acc[ni][2] + g1.x, acc[ni][3] + g1.y);
            }
        }
        gbar();

        // ---- P2: boundary gate + LSTM1 + state commit (h1,c1 scale + Ah split)
        for (int b = cta; b < B_; b += G) {
            const float* Yb = d_Y1 + (size_t)b * NA;
            float p = Yb[G4 + tid] * vs[tid] + Yb[G4 + 256 + tid] * vs[256 + tid];
            sm.red[tid] = p;
            __syncthreads();
            for (int off = 128; off > 0; off >>= 1) {
                if (tid < off) sm.red[tid] += sm.red[tid + off];
                __syncthreads();
            }
            float s = rintf(1.f / (1.f + expf(-sm.red[0])));
            if (tid == 0) d_s[b] = s;
            __syncthreads();
            for (int j = tid; j < H_; j += 256) {
                const int idx = b * H_ + j;
                float gi = Yb[j], gf = Yb[H_ + j], gg = Yb[2 * H_ + j], go = Yb[3 * H_ + j];
                float c = sigm(gf) * d_c1[idx] + sigm(gi) * tanhf(gg);
                float h = sigm(go) * tanhf(c);
                d_STH[b * K2 + j] = __float2half(h * s);   // lstm2 input (lo K half)
                float h1n = h * (1.f - s);
                d_c1[idx] = c * (1.f - s);
                __half hi = __float2half(h1n);
                __half lo = __float2half(h1n - __half2float(hi));
                d_AhH[idx] = hi;
                d_AhL[idx] = lo;
            }
        }
        gbar();

        // ---- P3: Y2 = [h1r*s | h2] @ [Wih2|Whh2]^T  (256 tiles of 64x32), 2-pass
        for (int tile = cta; tile < 256; tile += G) {
            const int m = tile & 1, n = tile >> 1;
            float acc[2][4];
#pragma unroll
            for (int j = 0; j < 2; j++)
#pragma unroll
                for (int q = 0; q < 4; q++) acc[j][q] = 0.f;
            tile_mm64<2>(d_STH + (size_t)(m * 64) * K2, nullptr, K2,
                         d_WbH + (size_t)(n * 32) * K2, d_WbL + (size_t)(n * 32) * K2, K2,
                         K2 / 32, sbase, acc, tid, wm2, wn2, rsel, csel);
#pragma unroll
            for (int ni = 0; ni < 2; ni++) {
                const int r0 = m * 64 + wm2 * 16 + (lane >> 2);
                const int c0 = n * 32 + wn2 * 16 + ni * 8 + (lane & 3) * 2;
                *reinterpret_cast<float2*>(&d_Y2[(size_t)r0 * G4 + c0]) =
                    make_float2(acc[ni][0], acc[ni][1]);
                *reinterpret_cast<float2*>(&d_Y2[(size_t)(r0 + 8) * G4 + c0]) =
                    make_float2(acc[ni][2], acc[ni][3]);
            }
        }
        gbar();
    }

    // trailing LSTM2 for t = T-1 (writes final output)
    do_p4(true);
}

// ---------------- fused prep kernels (2 launches total) ----------------------
__global__ void prep_state(const float* __restrict__ b1, const float* __restrict__ bbd)
{
    int i = blockIdx.x * blockDim.x + threadIdx.x;
    __half z = __float2half(0.f);
    if (i < B_ * H_) { d_c1[i] = 0.f; d_c2[i] = 0.f; d_AhH[i] = z; d_AhL[i] = z; }
    if (i < B_ * K2) d_STH[i] = z;
    if (i < 260) d_bars[i] = 0u;
    if (i < NA) d_bx[i] = (i < G4) ? b1[i] : bbd[i - G4];
}

// All 5 splits fused; region selected by linear index ranges.
// sizes: Wemb 2^21, Wx 4718592, Wh 4718592, Wb 2^23, Vid 2^24
__global__ void split_all(const float* __restrict__ Wemb,
                          const float* __restrict__ Wih1, const float* __restrict__ Wsi,
                          const float* __restrict__ Whh1, const float* __restrict__ Wsh,
                          const float* __restrict__ Wih2, const float* __restrict__ Whh2,
                          const float* __restrict__ video)
{
    const size_t SZ_WEMB = (size_t)H_ * F_;      // 2097152
    const size_t SZ_WX   = (size_t)NA * H_;      // 4718592
    const size_t SZ_WB   = (size_t)G4 * K2;      // 8388608
    const size_t SZ_VID  = (size_t)B_ * T_ * F_; // 16777216
    size_t idx = (size_t)blockIdx.x * blockDim.x + threadIdx.x;
    float v; __half *Hh, *Ll; size_t o;
    if (idx < SZ_WEMB) {
        o = idx; v = Wemb[o]; Hh = d_WembH; Ll = d_WembL;
    } else if ((idx -= SZ_WEMB) < SZ_WX) {
        o = idx;
        v = (o < (size_t)G4 * H_) ? Wih1[o] : Wsi[o - (size_t)G4 * H_];
        Hh = d_WxH; Ll = d_WxL;
    } else if ((idx -= SZ_WX) < SZ_WX) {
        o = idx;
        v = (o < (size_t)G4 * H_) ? Whh1[o] : Wsh[o - (size_t)G4 * H_];
        Hh = d_WhH; Ll = d_WhL;
    } else if ((idx -= SZ_WX) < SZ_WB) {
        o = idx;
        int n = (int)(o >> 11), k = (int)(o & (K2 - 1));
        v = (k < H_) ? Wih2[((size_t)n << 10) + k] : Whh2[((size_t)n << 10) + k - H_];
        Hh = d_WbH; Ll = d_WbL;
    } else if ((idx -= SZ_WB) < SZ_VID) {
        o = idx; v = video[o]; Hh = d_VidH; Ll = d_VidL;
    } else return;
    __half hi = __float2half(v);
    __half lo = __float2half(v - __half2float(hi));
    Hh[o] = hi; Ll[o] = lo;
}

// ---------------- launch -----------------------------------------------------
extern "C" void kernel_launch(void* const* d_in, const int* in_sizes, int n_in,
                              void* d_out, int out_size)
{
    const float* video = (const float*)d_in[0];
    const float* Wemb  = (const float*)d_in[1];
    const float* bemb  = (const float*)d_in[2];
    const float* Wih1  = (const float*)d_in[3];
    const float* Whh1  = (const float*)d_in[4];
    const float* b1    = (const float*)d_in[5];
    const float* Wsi   = (const float*)d_in[6];
    const float* Wsh   = (const float*)d_in[7];
    const float* bbd   = (const float*)d_in[8];
    const float* vs    = (const float*)d_in[9];
    const float* Wih2  = (const float*)d_in[10];
    const float* Whh2  = (const float*)d_in[11];

    __half *pVidH,*pVidL,*pWembH,*pWembL,*pVH,*pVL,*pWxH,*pWxL;
    float *pbx,*pGXZ;
    cudaGetSymbolAddress((void**)&pVidH, d_VidH);  cudaGetSymbolAddress((void**)&pVidL, d_VidL);
    cudaGetSymbolAddress((void**)&pWembH,d_WembH); cudaGetSymbolAddress((void**)&pWembL,d_WembL);
    cudaGetSymbolAddress((void**)&pVH,   d_VH);    cudaGetSymbolAddress((void**)&pVL,   d_VL);
    cudaGetSymbolAddress((void**)&pWxH,  d_WxH);   cudaGetSymbolAddress((void**)&pWxL,  d_WxL);
    cudaGetSymbolAddress((void**)&pbx,   d_bx);
    cudaGetSymbolAddress((void**)&pGXZ,  d_GXZ);

    cudaFuncSetAttribute(gemm_h<1,1,1,3>, cudaFuncAttributeMaxDynamicSharedMemorySize, SMEM_TOT);
    cudaFuncSetAttribute(gemm_h<1,0,0,2>, cudaFuncAttributeMaxDynamicSharedMemorySize, SMEM_TOT);
    cudaFuncSetAttribute(gemm_h<1,0,0,3>, cudaFuncAttributeMaxDynamicSharedMemorySize, SMEM_TOT);
    cudaFuncSetAttribute(scan_persist, cudaFuncAttributePreferredSharedMemoryCarveout,
                         cudaSharedmemCarveoutMaxShared);

    // deterministic grid: all CTAs resident (required by the spin barrier)
    int nsm = 148, occ = 2;
    cudaDeviceGetAttribute(&nsm, cudaDevAttrMultiProcessorCount, 0);
    cudaOccupancyMaxActiveBlocksPerMultiprocessor(&occ, scan_persist, 256, 0);
    if (occ < 1) occ = 1;
    if (occ > 2) occ = 2;
    const int G = nsm * occ;

    // launch #1: fused state/bias init
    prep_state<<<(B_*K2 + 255) / 256, 256>>>(b1, bbd);
    // launch #2: all fp16 hi/lo splits fused
    {
        const size_t total = (size_t)H_*F_ + 2*(size_t)NA*H_ + (size_t)G4*K2 + (size_t)B_*T_*F_;
        split_all<<<(int)((total + 255) / 256), 256>>>(Wemb, Wih1, Wsi, Whh1, Wsh, Wih2, Whh2, video);
    }

    // launch #3: V = relu(video @ Wemb^T + bemb) -> fp16 split (rows b*T+t), 3-pass
    gemm_h<1,1,1,3><<<dim3(H_/128, (B_*T_)/64), 256, SMEM_TOT>>>(
        pVidH, pVidL, (size_t)64 * F_, (size_t)128 * F_, F_,
        pWembH, pWembL, nullptr, bemb, pVH, pVL, F_, H_, 0);
    // launches #4,#5: GXZ = V @ [Wih1;Wsi]^T + [b1;b_bd]
    gemm_h<1,0,0,2><<<dim3(32, (B_*T_)/64), 256, SMEM_TOT>>>(
        pVH, pVL, (size_t)64 * T_ * H_, (size_t)H_, T_ * H_,
        pWxH, pWxL, pGXZ, pbx, nullptr, nullptr, H_, NA, 0);
    gemm_h<1,0,0,3><<<dim3(4, (B_*T_)/64), 256, SMEM_TOT>>>(
        pVH, pVL, (size_t)64 * T_ * H_, (size_t)H_, T_ * H_,
        pWxH, pWxL, pGXZ, pbx, nullptr, nullptr, H_, NA, 32);

    // launch #6 (ncu -s 5 target): persistent fused scan over T
    scan_persist<<<G, 256>>>(vs, (float*)d_out);
}

// round 16
// speedup vs baseline: 1.0385x; 1.0190x over previous
#include <cuda_runtime.h>
#include <cuda_fp16.h>
#include <math.h>
#include <stdint.h>

#define B_  128
#define T_  64
#define F_  2048
#define H_  1024
#define M_  512
#define G4  4096   // 4*H
#define NA  4608   // 4H + M
#define K2  2048   // 2H

// ---------------- device scratch (no allocations allowed) -------------------
__device__ __align__(128) __half d_VidH[(size_t)B_*T_*F_];
__device__ __align__(128) __half d_VidL[(size_t)B_*T_*F_];
__device__ __align__(128) __half d_WembH[(size_t)H_*F_];
__device__ __align__(128) __half d_WembL[(size_t)H_*F_];
__device__ __align__(128) __half d_VH[(size_t)B_*T_*H_];     // relu(embed) split, rows b*T+t
__device__ __align__(128) __half d_VL[(size_t)B_*T_*H_];
__device__ __align__(128) __half d_WxH[(size_t)NA*H_];       // [W_ih1; Wsi]
__device__ __align__(128) __half d_WxL[(size_t)NA*H_];
__device__ __align__(128) __half d_WhH[(size_t)NA*H_];       // [W_hh1; Wsh]
__device__ __align__(128) __half d_WhL[(size_t)NA*H_];
__device__ __align__(128) __half d_WbH[(size_t)G4*K2];       // [W_ih2 | W_hh2]
__device__ __align__(128) __half d_WbL[(size_t)G4*K2];
__device__ __align__(128) __half d_AhH[B_*H_];               // h1 split (Y1 A)
__device__ __align__(128) __half d_AhL[B_*H_];
__device__ __align__(128) __half d_STH[B_*K2];               // [h1r*s | h2] (Y2 A, hi only)

__device__ float d_bx [NA];
__device__ float d_GXZ[(size_t)B_*T_*NA];    // rows t*B+b
__device__ float d_Y1 [B_*NA];
__device__ float d_Y2 [B_*G4];
__device__ float d_c1 [B_*H_];
__device__ float d_c2 [B_*H_];
__device__ float d_s  [B_];
__device__ unsigned int d_bars[260];

// ---------------- asm helpers ------------------------------------------------
__device__ __forceinline__ uint32_t s2u_(const void* p) {
    uint32_t a;
    asm("{ .reg .u64 t; cvta.to.shared.u64 t, %1; cvt.u32.u64 %0, t; }" : "=r"(a) : "l"(p));
    return a;
}
__device__ __forceinline__ void cp16_(uint32_t d, const void* s) {
    asm volatile("cp.async.cg.shared.global [%0], [%1], 16;" :: "r"(d), "l"(s));
}
__device__ __forceinline__ void ldsm4_(uint32_t a, uint32_t& r0, uint32_t& r1, uint32_t& r2, uint32_t& r3) {
    asm volatile("ldmatrix.sync.aligned.m8n8.x4.shared.b16 {%0,%1,%2,%3}, [%4];"
                 : "=r"(r0), "=r"(r1), "=r"(r2), "=r"(r3) : "r"(a));
}
__device__ __forceinline__ void hmma_(float* c, const uint32_t* a, const uint32_t* b) {
    asm volatile("mma.sync.aligned.m16n8k16.row.col.f32.f16.f16.f32 "
                 "{%0,%1,%2,%3}, {%4,%5,%6,%7}, {%8,%9}, {%0,%1,%2,%3};"
                 : "+f"(c[0]), "+f"(c[1]), "+f"(c[2]), "+f"(c[3])
                 : "r"(a[0]), "r"(a[1]), "r"(a[2]), "r"(a[3]), "r"(b[0]), "r"(b[1]));
}
__device__ __forceinline__ float sigm(float x) { return 1.f / (1.f + expf(-x)); }

// ---------------- precompute HMMA GEMM: 128x128 tiles, BK=32, 2-stage --------
// 8 warps = 4M x 2N (warp 32 rows x 64 cols). PASSES=3: HH+HL+LH; 2: HH+HL.
// stage layout: A 256 rows (128 hi + 128 lo) x 80B = 20480; B 256 rows x 80B at +20480.
constexpr int PSTG = 40960;
constexpr int SMEM_TOT = 2 * PSTG;     // 81920

template<int HAS_BIAS, int RELU, int SPLIT_OUT, int PASSES>
__global__ __launch_bounds__(256)
void gemm_h(const __half* __restrict__ AH, const __half* __restrict__ AL,
            size_t tileStride, int lda,
            const __half* __restrict__ BH, const __half* __restrict__ BL,
            float* __restrict__ C,
            const float* __restrict__ bias,
            __half* __restrict__ OH, __half* __restrict__ OL,
            int K, int N, int bxOff)
{
    extern __shared__ __align__(128) char sm[];
    const uint32_t sb = s2u_(sm);
    const int tid  = threadIdx.x;
    const int lane = tid & 31;
    const int wid  = tid >> 5;
    const int wm   = wid & 3;          // 4 warps along M (32 rows each)
    const int wn   = wid >> 2;         // 2 warps along N (64 cols each)
    const int bx   = blockIdx.x + bxOff, by = blockIdx.y;

    const __half* gAH = AH + (size_t)by * tileStride;
    const __half* gAL = AL + (size_t)by * tileStride;
    const __half* gBH = BH + (size_t)bx * 128 * K;
    const __half* gBL = BL + (size_t)bx * 128 * K;

    float acc[2][8][4];
#pragma unroll
    for (int i = 0; i < 2; i++)
#pragma unroll
        for (int j = 0; j < 8; j++)
#pragma unroll
            for (int q = 0; q < 4; q++) acc[i][j][q] = 0.f;

    auto load_stage = [&](int p, int kt) {
        const uint32_t dst = sb + p * PSTG;
        const int k0 = kt * 32;
        // A: thread tid loads row tid (0..127 hi, 128..255 lo), 4 x 16B chunks
        if (PASSES == 3 || tid < 128) {
            const __half* src = (tid < 128) ? (gAH + (size_t)tid * lda)
                                            : (gAL + (size_t)(tid - 128) * lda);
#pragma unroll
            for (int col = 0; col < 4; col++)
                cp16_(dst + tid * 80 + col * 16, src + k0 + col * 8);
        }
        // B: thread tid loads row tid (0..127 hi, 128..255 lo), 4 x 16B chunks
        {
            const __half* src = (tid < 128) ? (gBH + (size_t)tid * K)
                                            : (gBL + (size_t)(tid - 128) * K);
#pragma unroll
            for (int col = 0; col < 4; col++)
                cp16_(dst + 20480 + tid * 80 + col * 16, src + k0 + col * 8);
        }
        asm volatile("cp.async.commit_group;" ::: "memory");
    };

    const int KT = K / 32;
    load_stage(0, 0);
    const int rsel = lane & 15, csel = lane >> 4;

    for (int kt = 0; kt < KT; kt++) {
        const int p = kt & 1;
        if (kt + 1 < KT) {
            load_stage(p ^ 1, kt + 1);
            asm volatile("cp.async.wait_group 1;" ::: "memory");
        } else {
            asm volatile("cp.async.wait_group 0;" ::: "memory");
        }
        __syncthreads();
        const uint32_t stg = sb + p * PSTG;
#pragma unroll
        for (int h = 0; h < 2; h++) {
            uint32_t aH[2][4], aL[2][4];
#pragma unroll
            for (int mi = 0; mi < 2; mi++) {
                uint32_t ad = stg + (wm * 32 + mi * 16 + rsel) * 80 + h * 32 + csel * 16;
                ldsm4_(ad, aH[mi][0], aH[mi][1], aH[mi][2], aH[mi][3]);
                if (PASSES == 3)
                    ldsm4_(ad + 10240, aL[mi][0], aL[mi][1], aL[mi][2], aL[mi][3]);
            }
#pragma unroll
            for (int g = 0; g < 4; g++) {
                uint32_t bd = stg + 20480 + (wn * 64 + g * 16 + rsel) * 80 + h * 32 + csel * 16;
                uint32_t t0, t1, t2, t3;
                uint32_t bH[2][2], bL[2][2];
                ldsm4_(bd, t0, t1, t2, t3);
                bH[0][0] = t0; bH[0][1] = t2; bH[1][0] = t1; bH[1][1] = t3;
                ldsm4_(bd + 10240, t0, t1, t2, t3);
                bL[0][0] = t0; bL[0][1] = t2; bL[1][0] = t1; bL[1][1] = t3;
#pragma unroll
                for (int mi = 0; mi < 2; mi++)
#pragma unroll
                    for (int nj = 0; nj < 2; nj++) {
                        float* a = acc[mi][g * 2 + nj];
                        hmma_(a, aH[mi], bH[nj]);
                        hmma_(a, aH[mi], bL[nj]);
                        if (PASSES == 3)
                            hmma_(a, aL[mi], bH[nj]);
                    }
            }
        }
        __syncthreads();
    }

#pragma unroll
    for (int mi = 0; mi < 2; mi++)
#pragma unroll
        for (int ni = 0; ni < 8; ni++) {
            const int row0 = by * 128 + wm * 32 + mi * 16 + (lane >> 2);
            const int col  = bx * 128 + wn * 64 + ni * 8 + (lane & 3) * 2;
            float v[4];
#pragma unroll
            for (int q = 0; q < 4; q++) v[q] = acc[mi][ni][q];
            if (HAS_BIAS) {
                float b0 = bias[col], b1 = bias[col + 1];
                v[0] += b0; v[1] += b1; v[2] += b0; v[3] += b1;
            }
            if (RELU) {
#pragma unroll
                for (int q = 0; q < 4; q++) v[q] = fmaxf(v[q], 0.f);
            }
            if (SPLIT_OUT) {
#pragma unroll
                for (int q = 0; q < 4; q++) {
                    int r = row0 + (q >> 1) * 8, c = col + (q & 1);
                    __half hi = __float2half(v[q]);
                    __half lo = __float2half(v[q] - __half2float(hi));
                    OH[(size_t)r * N + c] = hi;
                    OL[(size_t)r * N + c] = lo;
                }
            } else {
                *reinterpret_cast<float2*>(&C[(size_t)row0 * N + col])       = make_float2(v[0], v[1]);
                *reinterpret_cast<float2*>(&C[(size_t)(row0 + 8) * N + col]) = make_float2(v[2], v[3]);
            }
        }
}

// ---------------- persistent scan: 64x32 tiles, 8 warps (4M x 2N), 3-stage ---
// stage: A 128 rows (64 hi + 64 lo) x 80B = 10240; B 64 rows (32 hi + 32 lo) x 80B = 5120.
constexpr int SSTG = 15360;

struct ScanSmem {
    __align__(128) char stg[3][SSTG];
    float red[256];
};

template<int PASSES>
__device__ __forceinline__ void tile_mm64(
    const __half* __restrict__ AH, const __half* __restrict__ AL, int lda,
    const __half* __restrict__ BH, const __half* __restrict__ BL, int ldb,
    int KT, uint32_t sbase, float acc[2][4],
    int tid, int wm2, int wn2, int rsel, int csel)
{
    auto load_stage = [&](int p, int kt) {
        const uint32_t dst = sbase + p * SSTG;
        const int k0 = kt * 32;
        {   // A hi: 64 rows x 4 chunks = 256, one per thread
            int row = tid >> 2, col = tid & 3;
            cp16_(dst + row * 80 + col * 16, AH + (size_t)row * lda + k0 + col * 8);
            if (PASSES == 3)   // A lo at stage rows 64..127
                cp16_(dst + (64 + row) * 80 + col * 16, AL + (size_t)row * lda + k0 + col * 8);
        }
        {   // B: 64 rows (32 hi + 32 lo) x 4 = 256 chunks, one per thread
            int row = tid >> 2, col = tid & 3;
            const __half* src = (row < 32) ? BH + (size_t)row * ldb
                                           : BL + (size_t)(row - 32) * ldb;
            cp16_(dst + 10240 + row * 80 + col * 16, src + k0 + col * 8);
        }
        asm volatile("cp.async.commit_group;" ::: "memory");
    };

    load_stage(0, 0);
    if (KT > 1) load_stage(1, 1);

    for (int kt = 0; kt < KT; kt++) {
        if (kt + 2 < KT) {
            load_stage((kt + 2) % 3, kt + 2);
            asm volatile("cp.async.wait_group 2;" ::: "memory");
        } else if (kt + 1 < KT) {
            asm volatile("cp.async.wait_group 1;" ::: "memory");
        } else {
            asm volatile("cp.async.wait_group 0;" ::: "memory");
        }
        __syncthreads();

        const uint32_t stg = sbase + (kt % 3) * SSTG;
#pragma unroll
        for (int h = 0; h < 2; h++) {
            uint32_t aH[4], aL[4], bH[2][2], bL[2][2];
            {
                uint32_t ad = stg + (wm2 * 16 + rsel) * 80 + h * 32 + csel * 16;
                ldsm4_(ad, aH[0], aH[1], aH[2], aH[3]);
                if (PASSES == 3)
                    ldsm4_(ad + 5120, aL[0], aL[1], aL[2], aL[3]);
            }
            {
                uint32_t bd = stg + 10240 + (wn2 * 16 + rsel) * 80 + h * 32 + csel * 16;
                uint32_t t0, t1, t2, t3;
                ldsm4_(bd, t0, t1, t2, t3);
                bH[0][0] = t0; bH[0][1] = t2; bH[1][0] = t1; bH[1][1] = t3;
                ldsm4_(bd + 2560, t0, t1, t2, t3);
                bL[0][0] = t0; bL[0][1] = t2; bL[1][0] = t1; bL[1][1] = t3;
            }
#pragma unroll
            for (int ni = 0; ni < 2; ni++) {
                hmma_(acc[ni], aH, bH[ni]);
                hmma_(acc[ni], aH, bL[ni]);
                if (PASSES == 3)
                    hmma_(acc[ni], aL, bH[ni]);
            }
        }
        __syncthreads();
    }
}

__global__ __launch_bounds__(256, 2)
void scan_persist(const float* __restrict__ vs, float* __restrict__ out)
{
    __shared__ ScanSmem sm;
    const uint32_t sbase = s2u_(&sm.stg[0][0]);
    const int tid  = threadIdx.x;
    const int lane = tid & 31;
    const int wid  = tid >> 5;
    const int wm2  = wid & 3, wn2 = wid >> 2;
    const int rsel = lane & 15, csel = lane >> 4;
    const int cta  = blockIdx.x;
    const int G    = gridDim.x;
    int bar = 0;

    auto gbar = [&]() {
        __threadfence();
        __syncthreads();
        if (tid == 0) {
            atomicAdd(&d_bars[bar], 1u);
            while (*((volatile unsigned int*)&d_bars[bar]) < (unsigned)G) { }
        }
        bar++;
        __syncthreads();
        __threadfence();
    };

    // LSTM2 + c2/h2 commit (runs inside the NEXT step's P1 phase)
    auto do_p4 = [&](bool last) {
        const int b = cta - (G - B_);
        if (b >= 0 && b < B_) {
            const float* Yb = d_Y2 + (size_t)b * G4;
            for (int j = tid; j < H_; j += 256) {
                const int idx = b * H_ + j;
                float gi = Yb[j], gf = Yb[H_ + j], gg = Yb[2 * H_ + j], go = Yb[3 * H_ + j];
                float c = sigm(gf) * d_c2[idx] + sigm(gi) * tanhf(gg);
                float h = sigm(go) * tanhf(c);
                d_c2[idx] = c;
                d_STH[b * K2 + H_ + j] = __float2half(h);
                if (last) out[idx] = h;
            }
        }
    };

    for (int t = 0; t < T_; t++) {
        // ---- phase A: P4(t-1) + P1: Y1 = h1 @ [Whh1;Wsh]^T + GXZ[t] (288 tiles 64x32)
        if (t > 0) do_p4(false);
        for (int tile = cta; tile < 288; tile += G) {
            const int m = tile & 1, n = tile >> 1;
            float acc[2][4];
#pragma unroll
            for (int j = 0; j < 2; j++)
#pragma unroll
                for (int q = 0; q < 4; q++) acc[j][q] = 0.f;
            if (n >= 128)
                tile_mm64<3>(d_AhH + (size_t)(m * 64) * H_, d_AhL + (size_t)(m * 64) * H_, H_,
                             d_WhH + (size_t)(n * 32) * H_, d_WhL + (size_t)(n * 32) * H_, H_,
                             H_ / 32, sbase, acc, tid, wm2, wn2, rsel, csel);
            else
                tile_mm64<2>(d_AhH + (size_t)(m * 64) * H_, d_AhL + (size_t)(m * 64) * H_, H_,
                             d_WhH + (size_t)(n * 32) * H_, d_WhL + (size_t)(n * 32) * H_, H_,
                             H_ / 32, sbase, acc, tid, wm2, wn2, rsel, csel);
            const float* gx = d_GXZ + (size_t)t * B_ * NA;
#pragma unroll
            for (int ni = 0; ni < 2; ni++) {
                const int r0 = m * 64 + wm2 * 16 + (lane >> 2);
                const int c0 = n * 32 + wn2 * 16 + ni * 8 + (lane & 3) * 2;
                float2 g0 = *reinterpret_cast<const float2*>(&gx[(size_t)r0 * NA + c0]);
                float2 g1 = *reinterpret_cast<const float2*>(&gx[(size_t)(r0 + 8) * NA + c0]);
                *reinterpret_cast<float2*>(&d_Y1[(size_t)r0 * NA + c0]) =
                    make_float2(acc[ni][0] + g0.x, acc[ni][1] + g0.y);
                *reinterpret_cast<float2*>(&d_Y1[(size_t)(r0 + 8) * NA + c0]) =
                    make_float2(acc[ni][2] + g1.x, acc[ni][3] + g1.y);
            }
        }
        gbar();

        // ---- P2: boundary gate + LSTM1 + state commit (h1,c1 scale + Ah split)
        for (int b = cta; b < B_; b += G) {
            const float* Yb = d_Y1 + (size_t)b * NA;
            float p = Yb[G4 + tid] * vs[tid] + Yb[G4 + 256 + tid] * vs[256 + tid];
            sm.red[tid] = p;
            __syncthreads();
            for (int off = 128; off > 0; off >>= 1) {
                if (tid < off) sm.red[tid] += sm.red[tid + off];
                __syncthreads();
            }
            float s = rintf(1.f / (1.f + expf(-sm.red[0])));
            if (tid == 0) d_s[b] = s;
            __syncthreads();
            for (int j = tid; j < H_; j += 256) {
                const int idx = b * H_ + j;
                float gi = Yb[j], gf = Yb[H_ + j], gg = Yb[2 * H_ + j], go = Yb[3 * H_ + j];
                float c = sigm(gf) * d_c1[idx] + sigm(gi) * tanhf(gg);
                float h = sigm(go) * tanhf(c);
                d_STH[b * K2 + j] = __float2half(h * s);   // lstm2 input (lo K half)
                float h1n = h * (1.f - s);
                d_c1[idx] = c * (1.f - s);
                __half hi = __float2half(h1n);
                __half lo = __float2half(h1n - __half2float(hi));
                d_AhH[idx] = hi;
                d_AhL[idx] = lo;
            }
        }
        gbar();

        // ---- P3: Y2 = [h1r*s | h2] @ [Wih2|Whh2]^T  (256 tiles of 64x32), 2-pass
        for (int tile = cta; tile < 256; tile += G) {
            const int m = tile & 1, n = tile >> 1;
            float acc[2][4];
#pragma unroll
            for (int j = 0; j < 2; j++)
#pragma unroll
                for (int q = 0; q < 4; q++) acc[j][q] = 0.f;
            tile_mm64<2>(d_STH + (size_t)(m * 64) * K2, nullptr, K2,
                         d_WbH + (size_t)(n * 32) * K2, d_WbL + (size_t)(n * 32) * K2, K2,
                         K2 / 32, sbase, acc, tid, wm2, wn2, rsel, csel);
#pragma unroll
            for (int ni = 0; ni < 2; ni++) {
                const int r0 = m * 64 + wm2 * 16 + (lane >> 2);
                const int c0 = n * 32 + wn2 * 16 + ni * 8 + (lane & 3) * 2;
                *reinterpret_cast<float2*>(&d_Y2[(size_t)r0 * G4 + c0]) =
                    make_float2(acc[ni][0], acc[ni][1]);
                *reinterpret_cast<float2*>(&d_Y2[(size_t)(r0 + 8) * G4 + c0]) =
                    make_float2(acc[ni][2], acc[ni][3]);
            }
        }
        gbar();
    }

    // trailing LSTM2 for t = T-1 (writes final output)
    do_p4(true);
}

// ---------------- fused prep kernels (2 launches total) ----------------------
__global__ void prep_state(const float* __restrict__ b1, const float* __restrict__ bbd)
{
    int i = blockIdx.x * blockDim.x + threadIdx.x;
    __half z = __float2half(0.f);
    if (i < B_ * H_) { d_c1[i] = 0.f; d_c2[i] = 0.f; d_AhH[i] = z; d_AhL[i] = z; }
    if (i < B_ * K2) d_STH[i] = z;
    if (i < 260) d_bars[i] = 0u;
    if (i < NA) d_bx[i] = (i < G4) ? b1[i] : bbd[i - G4];
}

// All 5 splits fused; region selected by linear index ranges.
__global__ void split_all(const float* __restrict__ Wemb,
                          const float* __restrict__ Wih1, const float* __restrict__ Wsi,
                          const float* __restrict__ Whh1, const float* __restrict__ Wsh,
                          const float* __restrict__ Wih2, const float* __restrict__ Whh2,
                          const float* __restrict__ video)
{
    const size_t SZ_WEMB = (size_t)H_ * F_;
    const size_t SZ_WX   = (size_t)NA * H_;
    const size_t SZ_WB   = (size_t)G4 * K2;
    const size_t SZ_VID  = (size_t)B_ * T_ * F_;
    size_t idx = (size_t)blockIdx.x * blockDim.x + threadIdx.x;
    float v; __half *Hh, *Ll; size_t o;
    if (idx < SZ_WEMB) {
        o = idx; v = Wemb[o]; Hh = d_WembH; Ll = d_WembL;
    } else if ((idx -= SZ_WEMB) < SZ_WX) {
        o = idx;
        v = (o < (size_t)G4 * H_) ? Wih1[o] : Wsi[o - (size_t)G4 * H_];
        Hh = d_WxH; Ll = d_WxL;
    } else if ((idx -= SZ_WX) < SZ_WX) {
        o = idx;
        v = (o < (size_t)G4 * H_) ? Whh1[o] : Wsh[o - (size_t)G4 * H_];
        Hh = d_WhH; Ll = d_WhL;
    } else if ((idx -= SZ_WX) < SZ_WB) {
        o = idx;
        int n = (int)(o >> 11), k = (int)(o & (K2 - 1));
        v = (k < H_) ? Wih2[((size_t)n << 10) + k] : Whh2[((size_t)n << 10) + k - H_];
        Hh = d_WbH; Ll = d_WbL;
    } else if ((idx -= SZ_WB) < SZ_VID) {
        o = idx; v = video[o]; Hh = d_VidH; Ll = d_VidL;
    } else return;
    __half hi = __float2half(v);
    __half lo = __float2half(v - __half2float(hi));
    Hh[o] = hi; Ll[o] = lo;
}

// ---------------- launch -----------------------------------------------------
extern "C" void kernel_launch(void* const* d_in, const int* in_sizes, int n_in,
                              void* d_out, int out_size)
{
    const float* video = (const float*)d_in[0];
    const float* Wemb  = (const float*)d_in[1];
    const float* bemb  = (const float*)d_in[2];
    const float* Wih1  = (const float*)d_in[3];
    const float* Whh1  = (const float*)d_in[4];
    const float* b1    = (const float*)d_in[5];
    const float* Wsi   = (const float*)d_in[6];
    const float* Wsh   = (const float*)d_in[7];
    const float* bbd   = (const float*)d_in[8];
    const float* vs    = (const float*)d_in[9];
    const float* Wih2  = (const float*)d_in[10];
    const float* Whh2  = (const float*)d_in[11];

    __half *pVidH,*pVidL,*pWembH,*pWembL,*pVH,*pVL,*pWxH,*pWxL;
    float *pbx,*pGXZ;
    cudaGetSymbolAddress((void**)&pVidH, d_VidH);  cudaGetSymbolAddress((void**)&pVidL, d_VidL);
    cudaGetSymbolAddress((void**)&pWembH,d_WembH); cudaGetSymbolAddress((void**)&pWembL,d_WembL);
    cudaGetSymbolAddress((void**)&pVH,   d_VH);    cudaGetSymbolAddress((void**)&pVL,   d_VL);
    cudaGetSymbolAddress((void**)&pWxH,  d_WxH);   cudaGetSymbolAddress((void**)&pWxL,  d_WxL);
    cudaGetSymbolAddress((void**)&pbx,   d_bx);
    cudaGetSymbolAddress((void**)&pGXZ,  d_GXZ);

    cudaFuncSetAttribute(gemm_h<1,1,1,3>, cudaFuncAttributeMaxDynamicSharedMemorySize, SMEM_TOT);
    cudaFuncSetAttribute(gemm_h<1,0,0,2>, cudaFuncAttributeMaxDynamicSharedMemorySize, SMEM_TOT);
    cudaFuncSetAttribute(gemm_h<1,0,0,3>, cudaFuncAttributeMaxDynamicSharedMemorySize, SMEM_TOT);
    cudaFuncSetAttribute(scan_persist, cudaFuncAttributePreferredSharedMemoryCarveout,
                         cudaSharedmemCarveoutMaxShared);

    // deterministic grid: all CTAs resident (required by the spin barrier)
    int nsm = 148, occ = 2;
    cudaDeviceGetAttribute(&nsm, cudaDevAttrMultiProcessorCount, 0);
    cudaOccupancyMaxActiveBlocksPerMultiprocessor(&occ, scan_persist, 256, 0);
    if (occ < 1) occ = 1;
    if (occ > 2) occ = 2;
    const int G = nsm * occ;

    // launch #1: fused state/bias init
    prep_state<<<(B_*K2 + 255) / 256, 256>>>(b1, bbd);
    // launch #2: all fp16 hi/lo splits fused
    {
        const size_t total = (size_t)H_*F_ + 2*(size_t)NA*H_ + (size_t)G4*K2 + (size_t)B_*T_*F_;
        split_all<<<(int)((total + 255) / 256), 256>>>(Wemb, Wih1, Wsi, Whh1, Wsh, Wih2, Whh2, video);
    }

    // launch #3: V = relu(video @ Wemb^T + bemb) -> fp16 split (rows b*T+t), 3-pass
    gemm_h<1,1,1,3><<<dim3(H_/128, (B_*T_)/128), 256, SMEM_TOT>>>(
        pVidH, pVidL, (size_t)128 * F_, F_,
        pWembH, pWembL, nullptr, bemb, pVH, pVL, F_, H_, 0);
    // launches #4,#5: GXZ = V @ [Wih1;Wsi]^T + [b1;b_bd]
    // by tile covers output rows t=by, all b; A row b at V[(b*T+t)*H] -> tileStride=H, lda=T*H
    gemm_h<1,0,0,2><<<dim3(32, (B_*T_)/128), 256, SMEM_TOT>>>(
        pVH, pVL, (size_t)H_, T_ * H_,
        pWxH, pWxL, pGXZ, pbx, nullptr, nullptr, H_, NA, 0);
    gemm_h<1,0,0,3><<<dim3(4, (B_*T_)/128), 256, SMEM_TOT>>>(
        pVH, pVL, (size_t)H_, T_ * H_,
        pWxH, pWxL, pGXZ, pbx, nullptr, nullptr, H_, NA, 32);

    // launch #6 (ncu -s 5 target): persistent fused scan over T
    scan_persist<<<G, 256>>>(vs, (float*)d_out);
}